// round 1
// baseline (speedup 1.0000x reference)
#include <cuda_runtime.h>
#include <math_constants.h>

#define NN 50000
#define EE 800000
#define ETOT (EE + NN)
#define HC 128
#define FF 64

// ---------------- device scratch (static, no allocs) ----------------
__device__ int g_deg[NN];
__device__ int g_cur[NN];
__device__ int g_off[NN + 1];
__device__ int g_srcs[ETOT];
__device__ float g_xl[(size_t)NN * HC];
__device__ float g_xr[(size_t)NN * HC];
__device__ float g_feat[(size_t)NN * FF];
__device__ float g_y[(size_t)NN * FF];
__device__ float g_stats[2 * FF];

// ---------------- CSR build (counting sort by dst) ----------------
__global__ void k_zero() {
    int i = blockIdx.x * blockDim.x + threadIdx.x;
    if (i < NN) { g_deg[i] = 0; g_cur[i] = 0; }
}

__global__ void k_hist(const int* __restrict__ ei) {
    int e = blockIdx.x * blockDim.x + threadIdx.x;
    if (e < ETOT) {
        int d = (e < EE) ? ei[EE + e] : (e - EE);
        atomicAdd(&g_deg[d], 1);
    }
}

__global__ void k_scan() {
    __shared__ int sh[1024];
    __shared__ int s_carry;
    int tid = threadIdx.x;
    if (tid == 0) { s_carry = 0; g_off[0] = 0; }
    __syncthreads();
    for (int base = 0; base < NN; base += 1024) {
        int v = (base + tid < NN) ? g_deg[base + tid] : 0;
        sh[tid] = v;
        __syncthreads();
        for (int d = 1; d < 1024; d <<= 1) {
            int t = (tid >= d) ? sh[tid - d] : 0;
            __syncthreads();
            sh[tid] += t;
            __syncthreads();
        }
        if (base + tid < NN) g_off[base + tid + 1] = s_carry + sh[tid];
        __syncthreads();
        if (tid == 0) s_carry += sh[1023];
        __syncthreads();
    }
}

__global__ void k_scatter(const int* __restrict__ ei) {
    int e = blockIdx.x * blockDim.x + threadIdx.x;
    if (e < ETOT) {
        int s, d;
        if (e < EE) { s = ei[e]; d = ei[EE + e]; }
        else        { s = e - EE; d = e - EE; }
        int pos = g_off[d] + atomicAdd(&g_cur[d], 1);
        g_srcs[pos] = s;
    }
}

// ---------------- GEMM: xl = X @ Wl, xr = X @ Wr ----------------
// 64-row x 128-col tile per block, 256 threads, each thread 8x4 outputs.
// X == nullptr -> read g_feat (layers 2,3).
template <int K>
__global__ void k_gemm(const float* __restrict__ Xin,
                       const float* __restrict__ Wl,
                       const float* __restrict__ Wr) {
    __shared__ float sW[K][HC];
    __shared__ float sX[64][K];
    const float* X = Xin ? Xin : g_feat;
    const float* W = (blockIdx.y == 0) ? Wl : Wr;
    float* out = (blockIdx.y == 0) ? g_xl : g_xr;
    int tid = threadIdx.x;
    int row0 = blockIdx.x * 64;

    for (int idx = tid; idx < K * HC; idx += 256)
        sW[idx / HC][idx % HC] = W[idx];
    for (int idx = tid; idx < 64 * K; idx += 256) {
        int r = idx / K, k = idx % K;
        sX[r][k] = (row0 + r < NN) ? X[(size_t)(row0 + r) * K + k] : 0.f;
    }
    __syncthreads();

    int tx = tid & 31, ty = tid >> 5;
    float4 acc[8];
#pragma unroll
    for (int i = 0; i < 8; i++) acc[i] = make_float4(0.f, 0.f, 0.f, 0.f);

#pragma unroll 8
    for (int k = 0; k < K; k++) {
        float4 b = *(const float4*)&sW[k][tx * 4];
#pragma unroll
        for (int i = 0; i < 8; i++) {
            float a = sX[ty * 8 + i][k];
            acc[i].x += a * b.x;
            acc[i].y += a * b.y;
            acc[i].z += a * b.z;
            acc[i].w += a * b.w;
        }
    }
#pragma unroll
    for (int i = 0; i < 8; i++) {
        int r = row0 + ty * 8 + i;
        if (r < NN) *(float4*)&out[(size_t)r * HC + tx * 4] = acc[i];
    }
}

// ---------------- edge kernel: warp per dst node, online softmax ----------------
__global__ void k_edge(const float* __restrict__ att, const float* __restrict__ bias) {
    int warp = (blockIdx.x * blockDim.x + threadIdx.x) >> 5;
    int lane = threadIdx.x & 31;
    if (warp >= NN) return;
    int v = warp;
    int ch0 = lane * 4;

    float4 xr4 = *(const float4*)&g_xr[(size_t)v * HC + ch0];
    float4 att4 = *(const float4*)&att[ch0];

    float m = -CUDART_INF_F, z = 0.f;
    float4 acc = make_float4(0.f, 0.f, 0.f, 0.f);

    int beg = g_off[v], end = g_off[v + 1];
    for (int base = beg; base < end; base += 32) {
        int idx = base + lane;
        int sb = (idx < end) ? g_srcs[idx] : 0;
        int cnt = min(32, end - base);
        for (int t = 0; t < cnt; t++) {
            int s = __shfl_sync(0xffffffffu, sb, t);
            float4 xls = *(const float4*)&g_xl[(size_t)s * HC + ch0];
            float e0 = xls.x + xr4.x;
            float e1 = xls.y + xr4.y;
            float e2 = xls.z + xr4.z;
            float e3 = xls.w + xr4.w;
            // leaky relu, slope 0.2
            e0 = fmaxf(e0, 0.f) + 0.2f * fminf(e0, 0.f);
            e1 = fmaxf(e1, 0.f) + 0.2f * fminf(e1, 0.f);
            e2 = fmaxf(e2, 0.f) + 0.2f * fminf(e2, 0.f);
            e3 = fmaxf(e3, 0.f) + 0.2f * fminf(e3, 0.f);
            float p = e0 * att4.x + e1 * att4.y + e2 * att4.z + e3 * att4.w;
            // reduce within each 16-lane half (head)
            p += __shfl_xor_sync(0xffffffffu, p, 8);
            p += __shfl_xor_sync(0xffffffffu, p, 4);
            p += __shfl_xor_sync(0xffffffffu, p, 2);
            p += __shfl_xor_sync(0xffffffffu, p, 1);
            // online softmax update
            float mn = fmaxf(m, p);
            float sc = __expf(m - mn);
            float w = __expf(p - mn);
            z = z * sc + w;
            acc.x = acc.x * sc + w * xls.x;
            acc.y = acc.y * sc + w * xls.y;
            acc.z = acc.z * sc + w * xls.z;
            acc.w = acc.w * sc + w * xls.w;
            m = mn;
        }
    }

    float inv = 1.f / z;
    float rx = acc.x * inv, ry = acc.y * inv, rz = acc.z * inv, rw = acc.w * inv;
    float ox = __shfl_down_sync(0xffffffffu, rx, 16);
    float oy = __shfl_down_sync(0xffffffffu, ry, 16);
    float oz = __shfl_down_sync(0xffffffffu, rz, 16);
    float ow = __shfl_down_sync(0xffffffffu, rw, 16);
    if (lane < 16) {
        float4 bb = *(const float4*)&bias[ch0];
        float4 o;
        o.x = 0.5f * (rx + ox) + bb.x;
        o.y = 0.5f * (ry + oy) + bb.y;
        o.z = 0.5f * (rz + oz) + bb.z;
        o.w = 0.5f * (rw + ow) + bb.w;
        *(float4*)&g_y[(size_t)v * FF + ch0] = o;
    }
}

// ---------------- GraphNorm ----------------
__global__ void k_zero_stats() {
    int i = threadIdx.x;
    if (i < 2 * FF) g_stats[i] = 0.f;
}

__global__ void k_colstats() {
    __shared__ float sh1[256], sh2[256];
    int tid = threadIdx.x;
    int c = tid & 63;
    int rg = tid >> 6;
    float s = 0.f, s2 = 0.f;
    for (int r = blockIdx.x * 4 + rg; r < NN; r += gridDim.x * 4) {
        float v = g_y[(size_t)r * FF + c];
        s += v;
        s2 += v * v;
    }
    sh1[tid] = s; sh2[tid] = s2;
    __syncthreads();
    if (tid < 64) {
        s = sh1[tid] + sh1[tid + 64] + sh1[tid + 128] + sh1[tid + 192];
        s2 = sh2[tid] + sh2[tid + 64] + sh2[tid + 128] + sh2[tid + 192];
        atomicAdd(&g_stats[tid], s);
        atomicAdd(&g_stats[FF + tid], s2);
    }
}

// out == nullptr -> write g_feat (layers 1,2); else final d_out.
__global__ void k_norm(const float* __restrict__ gw, const float* __restrict__ gb,
                       const float* __restrict__ gm, float* __restrict__ outp) {
    int idx = blockIdx.x * blockDim.x + threadIdx.x;
    if (idx >= NN * FF) return;
    float* out = outp ? outp : g_feat;
    int c = idx & 63;
    const float invN = 1.f / (float)NN;
    float mu = g_stats[c] * invN;
    float ey2 = g_stats[FF + c] * invN;
    float gmc = gm[c];
    float var = ey2 - 2.f * gmc * mu * mu + gmc * gmc * mu * mu;
    float o = g_y[idx] - gmc * mu;
    float r = gw[c] * o * rsqrtf(var + 1e-5f) + gb[c];
    out[idx] = fmaxf(r, 0.f);
}

// ---------------- launch ----------------
extern "C" void kernel_launch(void* const* d_in, const int* in_sizes, int n_in,
                              void* d_out, int out_size) {
    const float* x = (const float*)d_in[0];
    const int* ei = (const int*)d_in[1];
    const float* P[3][7];
    for (int l = 0; l < 3; l++)
        for (int j = 0; j < 7; j++)
            P[l][j] = (const float*)d_in[2 + l * 7 + j];
    // j: 0 Wl, 1 Wr, 2 att, 3 b, 4 gw, 5 gb, 6 gm

    // CSR build (once per call; reused by all 3 layers)
    k_zero<<<(NN + 255) / 256, 256>>>();
    k_hist<<<(ETOT + 255) / 256, 256>>>(ei);
    k_scan<<<1, 1024>>>();
    k_scatter<<<(ETOT + 255) / 256, 256>>>(ei);

    dim3 ggrid((NN + 63) / 64, 2);
    int eblocks = (NN + 7) / 8;  // 8 warps/block, warp per node
    int nblocks = (NN * FF + 255) / 256;

    for (int l = 0; l < 3; l++) {
        if (l == 0) k_gemm<3><<<ggrid, 256>>>(x, P[0][0], P[0][1]);
        else        k_gemm<64><<<ggrid, 256>>>(nullptr, P[l][0], P[l][1]);
        k_edge<<<eblocks, 256>>>(P[l][2], P[l][3]);
        k_zero_stats<<<1, 128>>>();
        k_colstats<<<128, 256>>>();
        k_norm<<<nblocks, 256>>>(P[l][4], P[l][5], P[l][6],
                                 (l == 2) ? (float*)d_out : nullptr);
    }
}

// round 2
// speedup vs baseline: 1.1536x; 1.1536x over previous
#include <cuda_runtime.h>
#include <math_constants.h>

#define NN 50000
#define EE 800000
#define ETOT (EE + NN)
#define HC 128
#define FF 64

// ---------------- device scratch (static, no allocs) ----------------
__device__ int g_deg[NN];
__device__ int g_cur[NN];
__device__ int g_off[NN + 1];
__device__ int g_srcs[ETOT];
__device__ float g_xl[(size_t)NN * HC];
__device__ float g_xr[(size_t)NN * HC];
__device__ float g_y[(size_t)NN * FF];
__device__ float g_stats[3][2 * FF];

// ---------------- CSR build (counting sort by dst) ----------------
__global__ void k_zero() {
    int i = blockIdx.x * blockDim.x + threadIdx.x;
    if (i < NN) { g_deg[i] = 0; g_cur[i] = 0; }
    if (i < 3 * 2 * FF) ((float*)g_stats)[i] = 0.f;
}

__global__ void k_hist(const int* __restrict__ ei) {
    int e = blockIdx.x * blockDim.x + threadIdx.x;
    if (e < ETOT) {
        int d = (e < EE) ? ei[EE + e] : (e - EE);
        atomicAdd(&g_deg[d], 1);
    }
}

// single block, 1024 threads, warp-shfl scan per 1024-tile
__global__ void k_scan() {
    __shared__ int wsum[32];
    __shared__ int s_carry;
    int tid = threadIdx.x;
    int lane = tid & 31, wid = tid >> 5;
    if (tid == 0) { s_carry = 0; g_off[0] = 0; }
    __syncthreads();
    for (int base = 0; base < NN; base += 1024) {
        int v = (base + tid < NN) ? g_deg[base + tid] : 0;
        int s = v;
#pragma unroll
        for (int d = 1; d < 32; d <<= 1) {
            int t = __shfl_up_sync(0xffffffffu, s, d);
            if (lane >= d) s += t;
        }
        if (lane == 31) wsum[wid] = s;
        __syncthreads();
        if (wid == 0) {
            int w = wsum[lane];
#pragma unroll
            for (int d = 1; d < 32; d <<= 1) {
                int t = __shfl_up_sync(0xffffffffu, w, d);
                if (lane >= d) w += t;
            }
            wsum[lane] = w;
        }
        __syncthreads();
        int add = s_carry + (wid ? wsum[wid - 1] : 0);
        if (base + tid < NN) g_off[base + tid + 1] = add + s;
        __syncthreads();
        if (tid == 0) s_carry += wsum[31];
        __syncthreads();
    }
}

__global__ void k_scatter(const int* __restrict__ ei) {
    int e = blockIdx.x * blockDim.x + threadIdx.x;
    if (e < ETOT) {
        int s, d;
        if (e < EE) { s = ei[e]; d = ei[EE + e]; }
        else        { s = e - EE; d = e - EE; }
        int pos = g_off[d] + atomicAdd(&g_cur[d], 1);
        g_srcs[pos] = s;
    }
}

// ---------------- GEMM layer 1 (K=3, reads raw x) ----------------
__global__ void k_gemmA(const float* __restrict__ X,
                        const float* __restrict__ Wl,
                        const float* __restrict__ Wr) {
    __shared__ float sW[3][HC];
    __shared__ float sX[64][3];
    const float* W = (blockIdx.y == 0) ? Wl : Wr;
    float* out = (blockIdx.y == 0) ? g_xl : g_xr;
    int tid = threadIdx.x;
    int row0 = blockIdx.x * 64;

    for (int idx = tid; idx < 3 * HC; idx += 256)
        sW[idx / HC][idx % HC] = W[idx];
    for (int idx = tid; idx < 64 * 3; idx += 256) {
        int r = idx / 3, k = idx % 3;
        sX[r][k] = (row0 + r < NN) ? X[(size_t)(row0 + r) * 3 + k] : 0.f;
    }
    __syncthreads();

    int tx = tid & 31, ty = tid >> 5;
    float4 acc[8];
#pragma unroll
    for (int i = 0; i < 8; i++) acc[i] = make_float4(0.f, 0.f, 0.f, 0.f);
#pragma unroll
    for (int k = 0; k < 3; k++) {
        float4 b = *(const float4*)&sW[k][tx * 4];
#pragma unroll
        for (int i = 0; i < 8; i++) {
            float a = sX[ty * 8 + i][k];
            acc[i].x += a * b.x;
            acc[i].y += a * b.y;
            acc[i].z += a * b.z;
            acc[i].w += a * b.w;
        }
    }
#pragma unroll
    for (int i = 0; i < 8; i++) {
        int r = row0 + ty * 8 + i;
        if (r < NN) *(float4*)&out[(size_t)r * HC + tx * 4] = acc[i];
    }
}

// ---------------- GEMM layers 2,3 (K=64), fused GraphNorm+ReLU on X ----------------
// X comes from g_y (previous layer raw aggregation) + norm via stats.
// Pair-swizzled k-major X tile; packed fma.rn.f32x2 main loop.
#define SXIDX(k, r) (((k) << 6) + ((((((r) >> 1) ^ ((k) & 31))) << 1) | ((r) & 1)))

__global__ __launch_bounds__(256) void k_gemmB(
    const float* __restrict__ Wl, const float* __restrict__ Wr,
    const float* __restrict__ st, const float* __restrict__ gw,
    const float* __restrict__ gb, const float* __restrict__ gm) {
    __shared__ float sW[64 * HC];   // 32 KB
    __shared__ float sX[64 * 64];   // 16 KB, swizzled k-major
    __shared__ float sA[64], sB[64];
    int tid = threadIdx.x;
    const float* W = (blockIdx.y == 0) ? Wl : Wr;
    float* out = (blockIdx.y == 0) ? g_xl : g_xr;
    int row0 = blockIdx.x * 64;

    if (tid < 64) {
        const float invN = 1.f / (float)NN;
        float mu = st[tid] * invN;
        float ey2 = st[FF + tid] * invN;
        float gmc = gm[tid];
        float var = ey2 - 2.f * gmc * mu * mu + gmc * gmc * mu * mu;
        float al = gw[tid] * rsqrtf(var + 1e-5f);
        sA[tid] = al;
        sB[tid] = gb[tid] - al * gmc * mu;
    }
    for (int idx = tid; idx < 64 * HC; idx += 256) sW[idx] = W[idx];
    __syncthreads();
    for (int idx = tid; idx < 64 * 64; idx += 256) {
        int r = idx >> 6, k = idx & 63;
        float v = 0.f;
        if (row0 + r < NN) {
            float y = g_y[(size_t)(row0 + r) * FF + k];
            v = fmaxf(sA[k] * y + sB[k], 0.f);
        }
        sX[SXIDX(k, r)] = v;
    }
    __syncthreads();

    int tx = tid & 31, ty = tid >> 5;
    unsigned long long acc[4][4];
#pragma unroll
    for (int i = 0; i < 4; i++)
#pragma unroll
        for (int c = 0; c < 4; c++) acc[i][c] = 0ull;

#pragma unroll 4
    for (int k = 0; k < 64; k++) {
        float4 b4 = *(const float4*)&sW[k * HC + tx * 4];
        unsigned long long bs0, bs1, bs2, bs3;
        asm("mov.b64 %0, {%1,%1};" : "=l"(bs0) : "f"(b4.x));
        asm("mov.b64 %0, {%1,%1};" : "=l"(bs1) : "f"(b4.y));
        asm("mov.b64 %0, {%1,%1};" : "=l"(bs2) : "f"(b4.z));
        asm("mov.b64 %0, {%1,%1};" : "=l"(bs3) : "f"(b4.w));
#pragma unroll
        for (int i = 0; i < 4; i++) {
            unsigned long long a =
                *(const unsigned long long*)&sX[SXIDX(k, ty * 8 + 2 * i)];
            asm("fma.rn.f32x2 %0, %1, %2, %0;" : "+l"(acc[i][0]) : "l"(a), "l"(bs0));
            asm("fma.rn.f32x2 %0, %1, %2, %0;" : "+l"(acc[i][1]) : "l"(a), "l"(bs1));
            asm("fma.rn.f32x2 %0, %1, %2, %0;" : "+l"(acc[i][2]) : "l"(a), "l"(bs2));
            asm("fma.rn.f32x2 %0, %1, %2, %0;" : "+l"(acc[i][3]) : "l"(a), "l"(bs3));
        }
    }

#pragma unroll
    for (int i = 0; i < 4; i++) {
        int r = row0 + ty * 8 + 2 * i;
#pragma unroll
        for (int c = 0; c < 4; c++) {
            float lo, hi;
            asm("mov.b64 {%0,%1}, %2;" : "=f"(lo), "=f"(hi) : "l"(acc[i][c]));
            if (r < NN)     out[(size_t)r * HC + tx * 4 + c] = lo;
            if (r + 1 < NN) out[(size_t)(r + 1) * HC + tx * 4 + c] = hi;
        }
    }
}

// ---------------- edge kernel: warp per dst node, plain softmax (no max pass) ----------------
__global__ __launch_bounds__(256) void k_edge(const float* __restrict__ att,
                                              const float* __restrict__ bias) {
    int warp = (blockIdx.x * blockDim.x + threadIdx.x) >> 5;
    int lane = threadIdx.x & 31;
    if (warp >= NN) return;
    int v = warp;
    int ch0 = lane * 4;

    float4 xr4 = *(const float4*)&g_xr[(size_t)v * HC + ch0];
    float4 att4 = *(const float4*)&att[ch0];

    float z = 0.f;
    float4 acc = make_float4(0.f, 0.f, 0.f, 0.f);

#define EPROC(T)                                                               \
    {                                                                          \
        int s = __shfl_sync(0xffffffffu, sb, (T));                             \
        float4 xls = *(const float4*)&g_xl[(size_t)s * HC + ch0];              \
        float e0 = xls.x + xr4.x, e1 = xls.y + xr4.y;                          \
        float e2 = xls.z + xr4.z, e3 = xls.w + xr4.w;                          \
        e0 = fmaxf(e0, 0.2f * e0); e1 = fmaxf(e1, 0.2f * e1);                  \
        e2 = fmaxf(e2, 0.2f * e2); e3 = fmaxf(e3, 0.2f * e3);                  \
        float p = e0 * att4.x + e1 * att4.y + e2 * att4.z + e3 * att4.w;       \
        p += __shfl_xor_sync(0xffffffffu, p, 8);                               \
        p += __shfl_xor_sync(0xffffffffu, p, 4);                               \
        p += __shfl_xor_sync(0xffffffffu, p, 2);                               \
        p += __shfl_xor_sync(0xffffffffu, p, 1);                               \
        float w = __expf(fminf(p, 60.f));                                      \
        z += w;                                                                \
        acc.x += w * xls.x; acc.y += w * xls.y;                                \
        acc.z += w * xls.z; acc.w += w * xls.w;                                \
    }

    int beg = g_off[v], end = g_off[v + 1];
    for (int base = beg; base < end; base += 32) {
        int idx = base + lane;
        int sb = (idx < end) ? g_srcs[idx] : 0;
        int cnt = min(32, end - base);
        int t = 0;
        for (; t + 4 <= cnt; t += 4) {
            EPROC(t) EPROC(t + 1) EPROC(t + 2) EPROC(t + 3)
        }
        for (; t < cnt; t++) EPROC(t)
    }
#undef EPROC

    float inv = 1.f / z;
    float rx = acc.x * inv, ry = acc.y * inv, rz = acc.z * inv, rw = acc.w * inv;
    float ox = __shfl_down_sync(0xffffffffu, rx, 16);
    float oy = __shfl_down_sync(0xffffffffu, ry, 16);
    float oz = __shfl_down_sync(0xffffffffu, rz, 16);
    float ow = __shfl_down_sync(0xffffffffu, rw, 16);
    if (lane < 16) {
        float4 bb = *(const float4*)&bias[ch0];
        float4 o;
        o.x = 0.5f * (rx + ox) + bb.x;
        o.y = 0.5f * (ry + oy) + bb.y;
        o.z = 0.5f * (rz + oz) + bb.z;
        o.w = 0.5f * (rw + ow) + bb.w;
        *(float4*)&g_y[(size_t)v * FF + ch0] = o;
    }
}

// ---------------- column stats over g_y ----------------
__global__ void k_colstats(float* __restrict__ st) {
    __shared__ float sh1[256], sh2[256];
    int tid = threadIdx.x;
    int c = tid & 63;
    int rg = tid >> 6;
    float s = 0.f, s2 = 0.f;
    for (int r = blockIdx.x * 4 + rg; r < NN; r += gridDim.x * 4) {
        float v = g_y[(size_t)r * FF + c];
        s += v;
        s2 += v * v;
    }
    sh1[tid] = s; sh2[tid] = s2;
    __syncthreads();
    if (tid < 64) {
        s = sh1[tid] + sh1[tid + 64] + sh1[tid + 128] + sh1[tid + 192];
        s2 = sh2[tid] + sh2[tid + 64] + sh2[tid + 128] + sh2[tid + 192];
        atomicAdd(&st[tid], s);
        atomicAdd(&st[FF + tid], s2);
    }
}

// ---------------- final norm (layer 3) -> d_out ----------------
__global__ void k_norm(const float* __restrict__ st, const float* __restrict__ gw,
                       const float* __restrict__ gb, const float* __restrict__ gm,
                       float* __restrict__ out) {
    __shared__ float sA[64], sB[64];
    int tid = threadIdx.x;
    if (tid < 64) {
        const float invN = 1.f / (float)NN;
        float mu = st[tid] * invN;
        float ey2 = st[FF + tid] * invN;
        float gmc = gm[tid];
        float var = ey2 - 2.f * gmc * mu * mu + gmc * gmc * mu * mu;
        float al = gw[tid] * rsqrtf(var + 1e-5f);
        sA[tid] = al;
        sB[tid] = gb[tid] - al * gmc * mu;
    }
    __syncthreads();
    int idx = blockIdx.x * blockDim.x + tid;
    if (idx >= NN * FF) return;
    int c = idx & 63;
    out[idx] = fmaxf(sA[c] * g_y[idx] + sB[c], 0.f);
}

// ---------------- launch ----------------
extern "C" void kernel_launch(void* const* d_in, const int* in_sizes, int n_in,
                              void* d_out, int out_size) {
    const float* x = (const float*)d_in[0];
    const int* ei = (const int*)d_in[1];
    const float* P[3][7];
    for (int l = 0; l < 3; l++)
        for (int j = 0; j < 7; j++)
            P[l][j] = (const float*)d_in[2 + l * 7 + j];
    // j: 0 Wl, 1 Wr, 2 att, 3 b, 4 gw, 5 gb, 6 gm

    k_zero<<<(NN + 255) / 256, 256>>>();
    k_hist<<<(ETOT + 255) / 256, 256>>>(ei);
    k_scan<<<1, 1024>>>();
    k_scatter<<<(ETOT + 255) / 256, 256>>>(ei);

    dim3 ggrid((NN + 63) / 64, 2);
    int eblocks = (NN + 7) / 8;

    float* st0; float* st1; float* st2;
    // device symbol addresses resolved via kernel params (pass raw offsets)
    // use cudaGetSymbolAddress-free approach: we can take address inside kernels,
    // but for k_colstats/k_norm we pass pointers via a small helper kernel-safe trick:
    // simply use cudaMemcpyFromSymbol is not allowed in capture; instead pass
    // the stats slot index via pointer arithmetic on a device-symbol address
    // obtained at module scope is not possible host-side. So use a static
    // host-side cache of cudaGetSymbolAddress (pure address query, no alloc).
    static float* s_stats_base = nullptr;
    if (!s_stats_base) {
        void* p = nullptr;
        cudaGetSymbolAddress(&p, g_stats);
        s_stats_base = (float*)p;
    }
    st0 = s_stats_base;
    st1 = s_stats_base + 2 * FF;
    st2 = s_stats_base + 4 * FF;

    // layer 1
    k_gemmA<<<ggrid, 256>>>(x, P[0][0], P[0][1]);
    k_edge<<<eblocks, 256>>>(P[0][2], P[0][3]);
    k_colstats<<<128, 256>>>(st0);
    // layer 2 (norm of layer1 fused into gemm)
    k_gemmB<<<ggrid, 256>>>(P[1][0], P[1][1], st0, P[0][4], P[0][5], P[0][6]);
    k_edge<<<eblocks, 256>>>(P[1][2], P[1][3]);
    k_colstats<<<128, 256>>>(st1);
    // layer 3
    k_gemmB<<<ggrid, 256>>>(P[2][0], P[2][1], st1, P[1][4], P[1][5], P[1][6]);
    k_edge<<<eblocks, 256>>>(P[2][2], P[2][3]);
    k_colstats<<<128, 256>>>(st2);
    // final norm
    k_norm<<<(NN * FF + 255) / 256, 256>>>(st2, P[2][4], P[2][5], P[2][6],
                                           (float*)d_out);
}

// round 3
// speedup vs baseline: 1.2475x; 1.0814x over previous
#include <cuda_runtime.h>
#include <math_constants.h>

#define NN 50000
#define EE 800000
#define ETOT (EE + NN)
#define HC 128
#define FF 64
#define FULLMASK 0xffffffffu

// ---------------- device scratch (static, no allocs) ----------------
__device__ int g_deg[NN];
__device__ int g_cur[NN];
__device__ int g_off[NN + 1];
__device__ int g_srcs[ETOT];
__device__ float g_xl[(size_t)NN * HC];
__device__ float g_xr[(size_t)NN * HC];
__device__ float g_y[(size_t)NN * FF];
__device__ float g_stats[3][2 * FF];

// ---------------- CSR build ----------------
__global__ void k_zero() {
    int i = blockIdx.x * blockDim.x + threadIdx.x;
    if (i < NN) g_deg[i] = 1;  // self-loop pre-counted
    if (i < 3 * 2 * FF) ((float*)g_stats)[i] = 0.f;
}

__global__ void k_hist(const int* __restrict__ ei) {
    int e = 4 * (blockIdx.x * blockDim.x + threadIdx.x);
    if (e < EE) {
        int4 d4 = *(const int4*)&ei[EE + e];
        atomicAdd(&g_deg[d4.x], 1);
        atomicAdd(&g_deg[d4.y], 1);
        atomicAdd(&g_deg[d4.z], 1);
        atomicAdd(&g_deg[d4.w], 1);
    }
}

// single block, 1024 threads, warp-shfl scan; also emits scatter cursor
__global__ void k_scan() {
    __shared__ int wsum[32];
    __shared__ int s_carry;
    int tid = threadIdx.x;
    int lane = tid & 31, wid = tid >> 5;
    if (tid == 0) { s_carry = 0; g_off[0] = 0; }
    __syncthreads();
    for (int base = 0; base < NN; base += 1024) {
        int v = (base + tid < NN) ? g_deg[base + tid] : 0;
        int s = v;
#pragma unroll
        for (int d = 1; d < 32; d <<= 1) {
            int t = __shfl_up_sync(FULLMASK, s, d);
            if (lane >= d) s += t;
        }
        if (lane == 31) wsum[wid] = s;
        __syncthreads();
        if (wid == 0) {
            int w = wsum[lane];
#pragma unroll
            for (int d = 1; d < 32; d <<= 1) {
                int t = __shfl_up_sync(FULLMASK, w, d);
                if (lane >= d) w += t;
            }
            wsum[lane] = w;
        }
        __syncthreads();
        int add = s_carry + (wid ? wsum[wid - 1] : 0);
        if (base + tid < NN) {
            g_off[base + tid + 1] = add + s;
            g_cur[base + tid] = add + s - v;  // exclusive prefix = segment start
        }
        __syncthreads();
        if (tid == 0) s_carry += wsum[31];
        __syncthreads();
    }
}

__global__ void k_scatter(const int* __restrict__ ei) {
    int e = blockIdx.x * blockDim.x + threadIdx.x;
    if (e < ETOT) {
        int s, d;
        if (e < EE) { s = ei[e]; d = ei[EE + e]; }
        else        { s = e - EE; d = e - EE; }
        int pos = atomicAdd(&g_cur[d], 1);
        g_srcs[pos] = s;
    }
}

// ---------------- GEMM layer 1 (K=3, reads raw x) ----------------
__global__ void k_gemmA(const float* __restrict__ X,
                        const float* __restrict__ Wl,
                        const float* __restrict__ Wr) {
    __shared__ float sW[3][HC];
    __shared__ float sX[64][3];
    const float* W = (blockIdx.y == 0) ? Wl : Wr;
    float* out = (blockIdx.y == 0) ? g_xl : g_xr;
    int tid = threadIdx.x;
    int row0 = blockIdx.x * 64;

    for (int idx = tid; idx < 3 * HC; idx += 256)
        sW[idx / HC][idx % HC] = W[idx];
    for (int idx = tid; idx < 64 * 3; idx += 256) {
        int r = idx / 3, k = idx % 3;
        sX[r][k] = (row0 + r < NN) ? X[(size_t)(row0 + r) * 3 + k] : 0.f;
    }
    __syncthreads();

    int tx = tid & 31, ty = tid >> 5;
    float4 acc[8];
#pragma unroll
    for (int i = 0; i < 8; i++) acc[i] = make_float4(0.f, 0.f, 0.f, 0.f);
#pragma unroll
    for (int k = 0; k < 3; k++) {
        float4 b = *(const float4*)&sW[k][tx * 4];
#pragma unroll
        for (int i = 0; i < 8; i++) {
            float a = sX[ty * 8 + i][k];
            acc[i].x += a * b.x;
            acc[i].y += a * b.y;
            acc[i].z += a * b.z;
            acc[i].w += a * b.w;
        }
    }
#pragma unroll
    for (int i = 0; i < 8; i++) {
        int r = row0 + ty * 8 + i;
        if (r < NN) *(float4*)&out[(size_t)r * HC + tx * 4] = acc[i];
    }
}

// ---------------- GEMM layers 2,3 (K=64), fused GraphNorm+ReLU on X ----------------
#define SXIDX(k, r) (((k) << 6) + ((((((r) >> 1) ^ ((k) & 31))) << 1) | ((r) & 1)))

__global__ __launch_bounds__(256) void k_gemmB(
    const float* __restrict__ Wl, const float* __restrict__ Wr,
    const float* __restrict__ st, const float* __restrict__ gw,
    const float* __restrict__ gb, const float* __restrict__ gm) {
    __shared__ float sW[64 * HC];
    __shared__ float sX[64 * 64];
    __shared__ float sA[64], sB[64];
    int tid = threadIdx.x;
    const float* W = (blockIdx.y == 0) ? Wl : Wr;
    float* out = (blockIdx.y == 0) ? g_xl : g_xr;
    int row0 = blockIdx.x * 64;

    if (tid < 64) {
        const float invN = 1.f / (float)NN;
        float mu = st[tid] * invN;
        float ey2 = st[FF + tid] * invN;
        float gmc = gm[tid];
        float var = ey2 - 2.f * gmc * mu * mu + gmc * gmc * mu * mu;
        float al = gw[tid] * rsqrtf(var + 1e-5f);
        sA[tid] = al;
        sB[tid] = gb[tid] - al * gmc * mu;
    }
    for (int idx = tid; idx < 64 * HC; idx += 256) sW[idx] = W[idx];
    __syncthreads();
    for (int idx = tid; idx < 64 * 64; idx += 256) {
        int r = idx >> 6, k = idx & 63;
        float v = 0.f;
        if (row0 + r < NN) {
            float y = g_y[(size_t)(row0 + r) * FF + k];
            v = fmaxf(sA[k] * y + sB[k], 0.f);
        }
        sX[SXIDX(k, r)] = v;
    }
    __syncthreads();

    int tx = tid & 31, ty = tid >> 5;
    unsigned long long acc[4][4];
#pragma unroll
    for (int i = 0; i < 4; i++)
#pragma unroll
        for (int c = 0; c < 4; c++) acc[i][c] = 0ull;

#pragma unroll 4
    for (int k = 0; k < 64; k++) {
        float4 b4 = *(const float4*)&sW[k * HC + tx * 4];
        unsigned long long bs0, bs1, bs2, bs3;
        asm("mov.b64 %0, {%1,%1};" : "=l"(bs0) : "f"(b4.x));
        asm("mov.b64 %0, {%1,%1};" : "=l"(bs1) : "f"(b4.y));
        asm("mov.b64 %0, {%1,%1};" : "=l"(bs2) : "f"(b4.z));
        asm("mov.b64 %0, {%1,%1};" : "=l"(bs3) : "f"(b4.w));
#pragma unroll
        for (int i = 0; i < 4; i++) {
            unsigned long long a =
                *(const unsigned long long*)&sX[SXIDX(k, ty * 8 + 2 * i)];
            asm("fma.rn.f32x2 %0, %1, %2, %0;" : "+l"(acc[i][0]) : "l"(a), "l"(bs0));
            asm("fma.rn.f32x2 %0, %1, %2, %0;" : "+l"(acc[i][1]) : "l"(a), "l"(bs1));
            asm("fma.rn.f32x2 %0, %1, %2, %0;" : "+l"(acc[i][2]) : "l"(a), "l"(bs2));
            asm("fma.rn.f32x2 %0, %1, %2, %0;" : "+l"(acc[i][3]) : "l"(a), "l"(bs3));
        }
    }

#pragma unroll
    for (int i = 0; i < 4; i++) {
        int r = row0 + ty * 8 + 2 * i;
#pragma unroll
        for (int c = 0; c < 4; c++) {
            float lo, hi;
            asm("mov.b64 {%0,%1}, %2;" : "=f"(lo), "=f"(hi) : "l"(acc[i][c]));
            if (r < NN)     out[(size_t)r * HC + tx * 4 + c] = lo;
            if (r + 1 < NN) out[(size_t)(r + 1) * HC + tx * 4 + c] = hi;
        }
    }
}

// ---------------- edge kernel: warp per node, 2 edges/iter, fused stats ----------------
__device__ __forceinline__ float ex2(float x) {
    float r;
    asm("ex2.approx.f32 %0, %1;" : "=f"(r) : "f"(x));
    return r;
}

__global__ __launch_bounds__(256) void k_edge(const float* __restrict__ att,
                                              const float* __restrict__ bias,
                                              float* __restrict__ st) {
    __shared__ float sS[2 * FF];
    int tid = threadIdx.x;
    if (tid < 2 * FF) sS[tid] = 0.f;
    __syncthreads();

    int warp = tid >> 5;
    int lane = tid & 31;
    int v = blockIdx.x * 8 + warp;  // grid sized so v < NN always
    int half = lane >> 4;           // which edge of the pair
    int l16 = lane & 15;
    int ch0 = l16 * 8;              // 8 channels per lane

    const float LOG2E = 1.4426950408889634f;
    float4 attA = *(const float4*)&att[ch0];
    float4 attB = *(const float4*)&att[ch0 + 4];
    attA.x *= LOG2E; attA.y *= LOG2E; attA.z *= LOG2E; attA.w *= LOG2E;
    attB.x *= LOG2E; attB.y *= LOG2E; attB.z *= LOG2E; attB.w *= LOG2E;
    float4 xrA = *(const float4*)&g_xr[(size_t)v * HC + ch0];
    float4 xrB = *(const float4*)&g_xr[(size_t)v * HC + ch0 + 4];

    float z = 0.f;
    float4 accA = make_float4(0.f, 0.f, 0.f, 0.f);
    float4 accB = make_float4(0.f, 0.f, 0.f, 0.f);

#define PAIR(T)                                                                \
    {                                                                          \
        int eidx = 2 * (T) + half;                                             \
        bool valid = eidx < cnt;                                               \
        int s = __shfl_sync(FULLMASK, sb, eidx);                               \
        const float* xp = &g_xl[(size_t)s * HC + ch0];                         \
        float4 xa = *(const float4*)xp;                                        \
        float4 xb = *(const float4*)(xp + 4);                                  \
        float e, pa = 0.f, pb = 0.f;                                           \
        e = xa.x + xrA.x; e = fmaxf(e, 0.2f * e); pa = fmaf(e, attA.x, pa);    \
        e = xa.y + xrA.y; e = fmaxf(e, 0.2f * e); pa = fmaf(e, attA.y, pa);    \
        e = xa.z + xrA.z; e = fmaxf(e, 0.2f * e); pa = fmaf(e, attA.z, pa);    \
        e = xa.w + xrA.w; e = fmaxf(e, 0.2f * e); pa = fmaf(e, attA.w, pa);    \
        e = xb.x + xrB.x; e = fmaxf(e, 0.2f * e); pb = fmaf(e, attB.x, pb);    \
        e = xb.y + xrB.y; e = fmaxf(e, 0.2f * e); pb = fmaf(e, attB.y, pb);    \
        e = xb.z + xrB.z; e = fmaxf(e, 0.2f * e); pb = fmaf(e, attB.z, pb);    \
        e = xb.w + xrB.w; e = fmaxf(e, 0.2f * e); pb = fmaf(e, attB.w, pb);    \
        float p = pa + pb;                                                     \
        p += __shfl_xor_sync(FULLMASK, p, 4);                                  \
        p += __shfl_xor_sync(FULLMASK, p, 2);                                  \
        p += __shfl_xor_sync(FULLMASK, p, 1);                                  \
        float w = valid ? ex2(fminf(p, 126.f)) : 0.f;                          \
        z += w;                                                                \
        accA.x += w * xa.x; accA.y += w * xa.y;                                \
        accA.z += w * xa.z; accA.w += w * xa.w;                                \
        accB.x += w * xb.x; accB.y += w * xb.y;                                \
        accB.z += w * xb.z; accB.w += w * xb.w;                                \
    }

    int beg = g_off[v], end = g_off[v + 1];
    for (int base = beg; base < end; base += 32) {
        int idx = base + lane;
        int sb = (idx < end) ? g_srcs[idx] : 0;
        int cnt = min(32, end - base);
        int pairs = (cnt + 1) >> 1;
        int t = 0;
        for (; t + 2 <= pairs; t += 2) { PAIR(t) PAIR(t + 1) }
        if (t < pairs) PAIR(t)
    }
#undef PAIR

    // combine the two edge-halves
    z += __shfl_xor_sync(FULLMASK, z, 16);
    accA.x += __shfl_xor_sync(FULLMASK, accA.x, 16);
    accA.y += __shfl_xor_sync(FULLMASK, accA.y, 16);
    accA.z += __shfl_xor_sync(FULLMASK, accA.z, 16);
    accA.w += __shfl_xor_sync(FULLMASK, accA.w, 16);
    accB.x += __shfl_xor_sync(FULLMASK, accB.x, 16);
    accB.y += __shfl_xor_sync(FULLMASK, accB.y, 16);
    accB.z += __shfl_xor_sync(FULLMASK, accB.z, 16);
    accB.w += __shfl_xor_sync(FULLMASK, accB.w, 16);
    float inv = 1.f / z;
    float rA0 = accA.x * inv, rA1 = accA.y * inv, rA2 = accA.z * inv, rA3 = accA.w * inv;
    float rB0 = accB.x * inv, rB1 = accB.y * inv, rB2 = accB.z * inv, rB3 = accB.w * inv;
    // head combine: lane l16 pairs with l16^8
    float o0 = 0.5f * (rA0 + __shfl_xor_sync(FULLMASK, rA0, 8));
    float o1 = 0.5f * (rA1 + __shfl_xor_sync(FULLMASK, rA1, 8));
    float o2 = 0.5f * (rA2 + __shfl_xor_sync(FULLMASK, rA2, 8));
    float o3 = 0.5f * (rA3 + __shfl_xor_sync(FULLMASK, rA3, 8));
    float o4 = 0.5f * (rB0 + __shfl_xor_sync(FULLMASK, rB0, 8));
    float o5 = 0.5f * (rB1 + __shfl_xor_sync(FULLMASK, rB1, 8));
    float o6 = 0.5f * (rB2 + __shfl_xor_sync(FULLMASK, rB2, 8));
    float o7 = 0.5f * (rB3 + __shfl_xor_sync(FULLMASK, rB3, 8));

    if (half == 0 && l16 < 8) {
        float4 bbA = *(const float4*)&bias[ch0];
        float4 bbB = *(const float4*)&bias[ch0 + 4];
        o0 += bbA.x; o1 += bbA.y; o2 += bbA.z; o3 += bbA.w;
        o4 += bbB.x; o5 += bbB.y; o6 += bbB.z; o7 += bbB.w;
        float4 wa = make_float4(o0, o1, o2, o3);
        float4 wb = make_float4(o4, o5, o6, o7);
        *(float4*)&g_y[(size_t)v * FF + ch0] = wa;
        *(float4*)&g_y[(size_t)v * FF + ch0 + 4] = wb;
        atomicAdd(&sS[ch0 + 0], o0); atomicAdd(&sS[FF + ch0 + 0], o0 * o0);
        atomicAdd(&sS[ch0 + 1], o1); atomicAdd(&sS[FF + ch0 + 1], o1 * o1);
        atomicAdd(&sS[ch0 + 2], o2); atomicAdd(&sS[FF + ch0 + 2], o2 * o2);
        atomicAdd(&sS[ch0 + 3], o3); atomicAdd(&sS[FF + ch0 + 3], o3 * o3);
        atomicAdd(&sS[ch0 + 4], o4); atomicAdd(&sS[FF + ch0 + 4], o4 * o4);
        atomicAdd(&sS[ch0 + 5], o5); atomicAdd(&sS[FF + ch0 + 5], o5 * o5);
        atomicAdd(&sS[ch0 + 6], o6); atomicAdd(&sS[FF + ch0 + 6], o6 * o6);
        atomicAdd(&sS[ch0 + 7], o7); atomicAdd(&sS[FF + ch0 + 7], o7 * o7);
    }
    __syncthreads();
    if (tid < 2 * FF) atomicAdd(&st[tid], sS[tid]);
}

// ---------------- final norm (layer 3) -> d_out ----------------
__global__ void k_norm(const float* __restrict__ st, const float* __restrict__ gw,
                       const float* __restrict__ gb, const float* __restrict__ gm,
                       float* __restrict__ out) {
    __shared__ float sA[64], sB[64];
    int tid = threadIdx.x;
    if (tid < 64) {
        const float invN = 1.f / (float)NN;
        float mu = st[tid] * invN;
        float ey2 = st[FF + tid] * invN;
        float gmc = gm[tid];
        float var = ey2 - 2.f * gmc * mu * mu + gmc * gmc * mu * mu;
        float al = gw[tid] * rsqrtf(var + 1e-5f);
        sA[tid] = al;
        sB[tid] = gb[tid] - al * gmc * mu;
    }
    __syncthreads();
    int idx = blockIdx.x * blockDim.x + tid;
    if (idx >= NN * FF) return;
    int c = idx & 63;
    out[idx] = fmaxf(sA[c] * g_y[idx] + sB[c], 0.f);
}

// ---------------- launch ----------------
extern "C" void kernel_launch(void* const* d_in, const int* in_sizes, int n_in,
                              void* d_out, int out_size) {
    const float* x = (const float*)d_in[0];
    const int* ei = (const int*)d_in[1];
    const float* P[3][7];
    for (int l = 0; l < 3; l++)
        for (int j = 0; j < 7; j++)
            P[l][j] = (const float*)d_in[2 + l * 7 + j];
    // j: 0 Wl, 1 Wr, 2 att, 3 b, 4 gw, 5 gb, 6 gm

    static float* s_stats_base = nullptr;
    if (!s_stats_base) {
        void* p = nullptr;
        cudaGetSymbolAddress(&p, g_stats);
        s_stats_base = (float*)p;
    }
    float* st0 = s_stats_base;
    float* st1 = s_stats_base + 2 * FF;
    float* st2 = s_stats_base + 4 * FF;

    k_zero<<<(NN + 255) / 256, 256>>>();
    k_hist<<<(EE / 4 + 255) / 256, 256>>>(ei);
    k_scan<<<1, 1024>>>();
    k_scatter<<<(ETOT + 255) / 256, 256>>>(ei);

    dim3 ggrid((NN + 63) / 64, 2);
    int eblocks = NN / 8;  // 6250, exact

    // layer 1
    k_gemmA<<<ggrid, 256>>>(x, P[0][0], P[0][1]);
    k_edge<<<eblocks, 256>>>(P[0][2], P[0][3], st0);
    // layer 2 (norm of layer1 fused into gemm)
    k_gemmB<<<ggrid, 256>>>(P[1][0], P[1][1], st0, P[0][4], P[0][5], P[0][6]);
    k_edge<<<eblocks, 256>>>(P[1][2], P[1][3], st1);
    // layer 3
    k_gemmB<<<ggrid, 256>>>(P[2][0], P[2][1], st1, P[1][4], P[1][5], P[1][6]);
    k_edge<<<eblocks, 256>>>(P[2][2], P[2][3], st2);
    // final norm
    k_norm<<<(NN * FF + 255) / 256, 256>>>(st2, P[2][4], P[2][5], P[2][6],
                                           (float*)d_out);
}

// round 4
// speedup vs baseline: 1.2939x; 1.0371x over previous
#include <cuda_runtime.h>
#include <math_constants.h>

#define NN 50000
#define EE 800000
#define ETOT (EE + NN)
#define HC 128
#define FF 64
#define FULLMASK 0xffffffffu
#define NB 49  // ceil(NN/1024)

// ---------------- device scratch (static, no allocs) ----------------
__device__ int g_deg[NN];
__device__ int g_cur[NN];
__device__ int g_off[NN + 1];
__device__ int g_bsum[64];
__device__ int g_bpre[64];
__device__ int g_srcs[ETOT];
__device__ float g_xl[(size_t)NN * HC];
__device__ float g_xr[(size_t)NN * HC];
__device__ float g_y[(size_t)NN * FF];
__device__ float g_stats[3][2 * FF];

// ---------------- CSR build ----------------
__global__ void k_zero() {
    int i = blockIdx.x * blockDim.x + threadIdx.x;
    if (i < NN) g_deg[i] = 1;  // self-loop pre-counted
    if (i < 3 * 2 * FF) ((float*)g_stats)[i] = 0.f;
}

__global__ void k_hist(const int* __restrict__ ei) {
    int e = 4 * (blockIdx.x * blockDim.x + threadIdx.x);
    if (e < EE) {
        int4 d4 = *(const int4*)&ei[EE + e];
        atomicAdd(&g_deg[d4.x], 1);
        atomicAdd(&g_deg[d4.y], 1);
        atomicAdd(&g_deg[d4.z], 1);
        atomicAdd(&g_deg[d4.w], 1);
    }
}

// level 1: per-1024-block local inclusive scan -> g_off[i+1], block total -> g_bsum
__global__ void k_scan1() {
    __shared__ int wsum[32];
    int tid = threadIdx.x;
    int lane = tid & 31, wid = tid >> 5;
    int gi = blockIdx.x * 1024 + tid;
    int v = (gi < NN) ? g_deg[gi] : 0;
    int s = v;
#pragma unroll
    for (int d = 1; d < 32; d <<= 1) {
        int t = __shfl_up_sync(FULLMASK, s, d);
        if (lane >= d) s += t;
    }
    if (lane == 31) wsum[wid] = s;
    __syncthreads();
    if (wid == 0) {
        int w = wsum[lane];
#pragma unroll
        for (int d = 1; d < 32; d <<= 1) {
            int t = __shfl_up_sync(FULLMASK, w, d);
            if (lane >= d) w += t;
        }
        wsum[lane] = w;
    }
    __syncthreads();
    int incl = s + (wid ? wsum[wid - 1] : 0);
    if (gi < NN) g_off[gi + 1] = incl;  // local inclusive, fixed up in scan3
    if (tid == 1023) g_bsum[blockIdx.x] = incl;
}

// level 2: scan the <=64 block sums (1 block, 64 threads)
__global__ void k_scan2() {
    __shared__ int sh[64];
    int tid = threadIdx.x;
    int v = (tid < NB) ? g_bsum[tid] : 0;
    sh[tid] = v;
    __syncthreads();
#pragma unroll
    for (int d = 1; d < 64; d <<= 1) {
        int t = (tid >= d) ? sh[tid - d] : 0;
        __syncthreads();
        sh[tid] += t;
        __syncthreads();
    }
    g_bpre[tid] = sh[tid] - v;  // exclusive
    if (tid == 0) g_off[0] = 0;
}

// level 3: add block prefix; emit scatter cursor
__global__ void k_scan3() {
    int i = blockIdx.x * blockDim.x + threadIdx.x;
    if (i < NN) {
        int off = g_off[i + 1] + g_bpre[i >> 10];
        g_off[i + 1] = off;
        g_cur[i] = off - g_deg[i];
    }
}

__global__ void k_scatter(const int* __restrict__ ei) {
    int e = blockIdx.x * blockDim.x + threadIdx.x;
    if (e < ETOT) {
        int s, d;
        if (e < EE) { s = ei[e]; d = ei[EE + e]; }
        else        { s = e - EE; d = e - EE; }
        int pos = atomicAdd(&g_cur[d], 1);
        g_srcs[pos] = s;
    }
}

// ---------------- GEMM layer 1 (K=3, reads raw x) ----------------
__global__ void k_gemmA(const float* __restrict__ X,
                        const float* __restrict__ Wl,
                        const float* __restrict__ Wr) {
    __shared__ float sW[3][HC];
    __shared__ float sX[64][3];
    const float* W = (blockIdx.y == 0) ? Wl : Wr;
    float* out = (blockIdx.y == 0) ? g_xl : g_xr;
    int tid = threadIdx.x;
    int row0 = blockIdx.x * 64;

    for (int idx = tid; idx < 3 * HC; idx += 256)
        sW[idx / HC][idx % HC] = W[idx];
    for (int idx = tid; idx < 64 * 3; idx += 256) {
        int r = idx / 3, k = idx % 3;
        sX[r][k] = (row0 + r < NN) ? X[(size_t)(row0 + r) * 3 + k] : 0.f;
    }
    __syncthreads();

    int tx = tid & 31, ty = tid >> 5;
    float4 acc[8];
#pragma unroll
    for (int i = 0; i < 8; i++) acc[i] = make_float4(0.f, 0.f, 0.f, 0.f);
#pragma unroll
    for (int k = 0; k < 3; k++) {
        float4 b = *(const float4*)&sW[k][tx * 4];
#pragma unroll
        for (int i = 0; i < 8; i++) {
            float a = sX[ty * 8 + i][k];
            acc[i].x += a * b.x;
            acc[i].y += a * b.y;
            acc[i].z += a * b.z;
            acc[i].w += a * b.w;
        }
    }
#pragma unroll
    for (int i = 0; i < 8; i++) {
        int r = row0 + ty * 8 + i;
        if (r < NN) *(float4*)&out[(size_t)r * HC + tx * 4] = acc[i];
    }
}

// ---------------- GEMM layers 2,3 (K=64), fused GraphNorm+ReLU on X ----------------
#define SXIDX(k, r) (((k) << 6) + ((((((r) >> 1) ^ ((k) & 31))) << 1) | ((r) & 1)))

__global__ __launch_bounds__(256) void k_gemmB(
    const float* __restrict__ Wl, const float* __restrict__ Wr,
    const float* __restrict__ st, const float* __restrict__ gw,
    const float* __restrict__ gb, const float* __restrict__ gm) {
    __shared__ float sW[64 * HC];
    __shared__ float sX[64 * 64];
    __shared__ float sA[64], sB[64];
    int tid = threadIdx.x;
    const float* W = (blockIdx.y == 0) ? Wl : Wr;
    float* out = (blockIdx.y == 0) ? g_xl : g_xr;
    int row0 = blockIdx.x * 64;

    if (tid < 64) {
        const float invN = 1.f / (float)NN;
        float mu = st[tid] * invN;
        float ey2 = st[FF + tid] * invN;
        float gmc = gm[tid];
        float var = ey2 - 2.f * gmc * mu * mu + gmc * gmc * mu * mu;
        float al = gw[tid] * rsqrtf(var + 1e-5f);
        sA[tid] = al;
        sB[tid] = gb[tid] - al * gmc * mu;
    }
    for (int idx = tid; idx < 64 * HC; idx += 256) sW[idx] = W[idx];
    __syncthreads();
    for (int idx = tid; idx < 64 * 64; idx += 256) {
        int r = idx >> 6, k = idx & 63;
        float v = 0.f;
        if (row0 + r < NN) {
            float y = g_y[(size_t)(row0 + r) * FF + k];
            v = fmaxf(sA[k] * y + sB[k], 0.f);
        }
        sX[SXIDX(k, r)] = v;
    }
    __syncthreads();

    int tx = tid & 31, ty = tid >> 5;
    unsigned long long acc[4][4];
#pragma unroll
    for (int i = 0; i < 4; i++)
#pragma unroll
        for (int c = 0; c < 4; c++) acc[i][c] = 0ull;

#pragma unroll 4
    for (int k = 0; k < 64; k++) {
        float4 b4 = *(const float4*)&sW[k * HC + tx * 4];
        unsigned long long bs0, bs1, bs2, bs3;
        asm("mov.b64 %0, {%1,%1};" : "=l"(bs0) : "f"(b4.x));
        asm("mov.b64 %0, {%1,%1};" : "=l"(bs1) : "f"(b4.y));
        asm("mov.b64 %0, {%1,%1};" : "=l"(bs2) : "f"(b4.z));
        asm("mov.b64 %0, {%1,%1};" : "=l"(bs3) : "f"(b4.w));
#pragma unroll
        for (int i = 0; i < 4; i++) {
            unsigned long long a =
                *(const unsigned long long*)&sX[SXIDX(k, ty * 8 + 2 * i)];
            asm("fma.rn.f32x2 %0, %1, %2, %0;" : "+l"(acc[i][0]) : "l"(a), "l"(bs0));
            asm("fma.rn.f32x2 %0, %1, %2, %0;" : "+l"(acc[i][1]) : "l"(a), "l"(bs1));
            asm("fma.rn.f32x2 %0, %1, %2, %0;" : "+l"(acc[i][2]) : "l"(a), "l"(bs2));
            asm("fma.rn.f32x2 %0, %1, %2, %0;" : "+l"(acc[i][3]) : "l"(a), "l"(bs3));
        }
    }

#pragma unroll
    for (int i = 0; i < 4; i++) {
        int r = row0 + ty * 8 + 2 * i;
#pragma unroll
        for (int c = 0; c < 4; c++) {
            float lo, hi;
            asm("mov.b64 {%0,%1}, %2;" : "=f"(lo), "=f"(hi) : "l"(acc[i][c]));
            if (r < NN)     out[(size_t)r * HC + tx * 4 + c] = lo;
            if (r + 1 < NN) out[(size_t)(r + 1) * HC + tx * 4 + c] = hi;
        }
    }
}

// ---------------- edge kernel: warp per node, 2 edges/iter, fused stats ----------------
__device__ __forceinline__ float ex2(float x) {
    float r;
    asm("ex2.approx.f32 %0, %1;" : "=f"(r) : "f"(x));
    return r;
}

__global__ __launch_bounds__(512) void k_edge(const float* __restrict__ att,
                                              const float* __restrict__ bias,
                                              float* __restrict__ st) {
    __shared__ float sS[2 * FF];
    int tid = threadIdx.x;
    if (tid < 2 * FF) sS[tid] = 0.f;
    __syncthreads();

    int warp = tid >> 5;
    int lane = tid & 31;
    int v = blockIdx.x * 16 + warp;  // grid sized so v < NN always
    int half = lane >> 4;
    int l16 = lane & 15;
    int ch0 = l16 * 8;

    const float LOG2E = 1.4426950408889634f;
    float4 attA = *(const float4*)&att[ch0];
    float4 attB = *(const float4*)&att[ch0 + 4];
    attA.x *= LOG2E; attA.y *= LOG2E; attA.z *= LOG2E; attA.w *= LOG2E;
    attB.x *= LOG2E; attB.y *= LOG2E; attB.z *= LOG2E; attB.w *= LOG2E;
    float4 xrA = *(const float4*)&g_xr[(size_t)v * HC + ch0];
    float4 xrB = *(const float4*)&g_xr[(size_t)v * HC + ch0 + 4];

    float z = 0.f;
    float4 accA = make_float4(0.f, 0.f, 0.f, 0.f);
    float4 accB = make_float4(0.f, 0.f, 0.f, 0.f);

#define PAIR(T)                                                                \
    {                                                                          \
        int eidx = 2 * (T) + half;                                             \
        bool valid = eidx < cnt;                                               \
        int s = __shfl_sync(FULLMASK, sb, eidx);                               \
        const float* xp = &g_xl[(size_t)s * HC + ch0];                         \
        float4 xa = *(const float4*)xp;                                        \
        float4 xb = *(const float4*)(xp + 4);                                  \
        float e, pa = 0.f, pb = 0.f;                                           \
        e = xa.x + xrA.x; e = fmaxf(e, 0.2f * e); pa = fmaf(e, attA.x, pa);    \
        e = xa.y + xrA.y; e = fmaxf(e, 0.2f * e); pa = fmaf(e, attA.y, pa);    \
        e = xa.z + xrA.z; e = fmaxf(e, 0.2f * e); pa = fmaf(e, attA.z, pa);    \
        e = xa.w + xrA.w; e = fmaxf(e, 0.2f * e); pa = fmaf(e, attA.w, pa);    \
        e = xb.x + xrB.x; e = fmaxf(e, 0.2f * e); pb = fmaf(e, attB.x, pb);    \
        e = xb.y + xrB.y; e = fmaxf(e, 0.2f * e); pb = fmaf(e, attB.y, pb);    \
        e = xb.z + xrB.z; e = fmaxf(e, 0.2f * e); pb = fmaf(e, attB.z, pb);    \
        e = xb.w + xrB.w; e = fmaxf(e, 0.2f * e); pb = fmaf(e, attB.w, pb);    \
        float p = pa + pb;                                                     \
        p += __shfl_xor_sync(FULLMASK, p, 4);                                  \
        p += __shfl_xor_sync(FULLMASK, p, 2);                                  \
        p += __shfl_xor_sync(FULLMASK, p, 1);                                  \
        float w = valid ? ex2(fminf(p, 126.f)) : 0.f;                          \
        z += w;                                                                \
        accA.x += w * xa.x; accA.y += w * xa.y;                                \
        accA.z += w * xa.z; accA.w += w * xa.w;                                \
        accB.x += w * xb.x; accB.y += w * xb.y;                                \
        accB.z += w * xb.z; accB.w += w * xb.w;                                \
    }

    int beg = g_off[v], end = g_off[v + 1];
    for (int base = beg; base < end; base += 32) {
        int idx = base + lane;
        int sb = (idx < end) ? g_srcs[idx] : 0;
        int cnt = min(32, end - base);
        int pairs = (cnt + 1) >> 1;
        int t = 0;
        for (; t + 2 <= pairs; t += 2) { PAIR(t) PAIR(t + 1) }
        if (t < pairs) PAIR(t)
    }
#undef PAIR

    z += __shfl_xor_sync(FULLMASK, z, 16);
    accA.x += __shfl_xor_sync(FULLMASK, accA.x, 16);
    accA.y += __shfl_xor_sync(FULLMASK, accA.y, 16);
    accA.z += __shfl_xor_sync(FULLMASK, accA.z, 16);
    accA.w += __shfl_xor_sync(FULLMASK, accA.w, 16);
    accB.x += __shfl_xor_sync(FULLMASK, accB.x, 16);
    accB.y += __shfl_xor_sync(FULLMASK, accB.y, 16);
    accB.z += __shfl_xor_sync(FULLMASK, accB.z, 16);
    accB.w += __shfl_xor_sync(FULLMASK, accB.w, 16);
    float inv = 1.f / z;
    float rA0 = accA.x * inv, rA1 = accA.y * inv, rA2 = accA.z * inv, rA3 = accA.w * inv;
    float rB0 = accB.x * inv, rB1 = accB.y * inv, rB2 = accB.z * inv, rB3 = accB.w * inv;
    float o0 = 0.5f * (rA0 + __shfl_xor_sync(FULLMASK, rA0, 8));
    float o1 = 0.5f * (rA1 + __shfl_xor_sync(FULLMASK, rA1, 8));
    float o2 = 0.5f * (rA2 + __shfl_xor_sync(FULLMASK, rA2, 8));
    float o3 = 0.5f * (rA3 + __shfl_xor_sync(FULLMASK, rA3, 8));
    float o4 = 0.5f * (rB0 + __shfl_xor_sync(FULLMASK, rB0, 8));
    float o5 = 0.5f * (rB1 + __shfl_xor_sync(FULLMASK, rB1, 8));
    float o6 = 0.5f * (rB2 + __shfl_xor_sync(FULLMASK, rB2, 8));
    float o7 = 0.5f * (rB3 + __shfl_xor_sync(FULLMASK, rB3, 8));

    if (half == 0 && l16 < 8) {
        float4 bbA = *(const float4*)&bias[ch0];
        float4 bbB = *(const float4*)&bias[ch0 + 4];
        o0 += bbA.x; o1 += bbA.y; o2 += bbA.z; o3 += bbA.w;
        o4 += bbB.x; o5 += bbB.y; o6 += bbB.z; o7 += bbB.w;
        *(float4*)&g_y[(size_t)v * FF + ch0] = make_float4(o0, o1, o2, o3);
        *(float4*)&g_y[(size_t)v * FF + ch0 + 4] = make_float4(o4, o5, o6, o7);
        atomicAdd(&sS[ch0 + 0], o0); atomicAdd(&sS[FF + ch0 + 0], o0 * o0);
        atomicAdd(&sS[ch0 + 1], o1); atomicAdd(&sS[FF + ch0 + 1], o1 * o1);
        atomicAdd(&sS[ch0 + 2], o2); atomicAdd(&sS[FF + ch0 + 2], o2 * o2);
        atomicAdd(&sS[ch0 + 3], o3); atomicAdd(&sS[FF + ch0 + 3], o3 * o3);
        atomicAdd(&sS[ch0 + 4], o4); atomicAdd(&sS[FF + ch0 + 4], o4 * o4);
        atomicAdd(&sS[ch0 + 5], o5); atomicAdd(&sS[FF + ch0 + 5], o5 * o5);
        atomicAdd(&sS[ch0 + 6], o6); atomicAdd(&sS[FF + ch0 + 6], o6 * o6);
        atomicAdd(&sS[ch0 + 7], o7); atomicAdd(&sS[FF + ch0 + 7], o7 * o7);
    }
    __syncthreads();
    if (tid < 2 * FF) atomicAdd(&st[tid], sS[tid]);
}

// ---------------- final norm (layer 3) -> d_out, float4 ----------------
__global__ void k_norm(const float* __restrict__ st, const float* __restrict__ gw,
                       const float* __restrict__ gb, const float* __restrict__ gm,
                       float* __restrict__ out) {
    __shared__ float sA[64], sB[64];
    int tid = threadIdx.x;
    if (tid < 64) {
        const float invN = 1.f / (float)NN;
        float mu = st[tid] * invN;
        float ey2 = st[FF + tid] * invN;
        float gmc = gm[tid];
        float var = ey2 - 2.f * gmc * mu * mu + gmc * gmc * mu * mu;
        float al = gw[tid] * rsqrtf(var + 1e-5f);
        sA[tid] = al;
        sB[tid] = gb[tid] - al * gmc * mu;
    }
    __syncthreads();
    int idx = blockIdx.x * blockDim.x + tid;
    if (idx >= NN * FF / 4) return;
    int c = (idx * 4) & 63;
    float4 y = *(const float4*)&g_y[idx * 4];
    float4 o;
    o.x = fmaxf(sA[c + 0] * y.x + sB[c + 0], 0.f);
    o.y = fmaxf(sA[c + 1] * y.y + sB[c + 1], 0.f);
    o.z = fmaxf(sA[c + 2] * y.z + sB[c + 2], 0.f);
    o.w = fmaxf(sA[c + 3] * y.w + sB[c + 3], 0.f);
    *(float4*)&out[idx * 4] = o;
}

// ---------------- launch ----------------
extern "C" void kernel_launch(void* const* d_in, const int* in_sizes, int n_in,
                              void* d_out, int out_size) {
    const float* x = (const float*)d_in[0];
    const int* ei = (const int*)d_in[1];
    const float* P[3][7];
    for (int l = 0; l < 3; l++)
        for (int j = 0; j < 7; j++)
            P[l][j] = (const float*)d_in[2 + l * 7 + j];
    // j: 0 Wl, 1 Wr, 2 att, 3 b, 4 gw, 5 gb, 6 gm

    static float* s_stats_base = nullptr;
    if (!s_stats_base) {
        void* p = nullptr;
        cudaGetSymbolAddress(&p, g_stats);
        s_stats_base = (float*)p;
    }
    float* st0 = s_stats_base;
    float* st1 = s_stats_base + 2 * FF;
    float* st2 = s_stats_base + 4 * FF;

    k_zero<<<(NN + 255) / 256, 256>>>();
    k_hist<<<(EE / 4 + 255) / 256, 256>>>(ei);
    k_scan1<<<NB, 1024>>>();
    k_scan2<<<1, 64>>>();
    k_scan3<<<(NN + 255) / 256, 256>>>();
    k_scatter<<<(ETOT + 255) / 256, 256>>>(ei);

    dim3 ggrid((NN + 63) / 64, 2);
    int eblocks = (NN + 15) / 16;  // 3125, exact

    // layer 1
    k_gemmA<<<ggrid, 256>>>(x, P[0][0], P[0][1]);
    k_edge<<<eblocks, 512>>>(P[0][2], P[0][3], st0);
    // layer 2 (norm of layer1 fused into gemm)
    k_gemmB<<<ggrid, 256>>>(P[1][0], P[1][1], st0, P[0][4], P[0][5], P[0][6]);
    k_edge<<<eblocks, 512>>>(P[1][2], P[1][3], st1);
    // layer 3
    k_gemmB<<<ggrid, 256>>>(P[2][0], P[2][1], st1, P[1][4], P[1][5], P[1][6]);
    k_edge<<<eblocks, 512>>>(P[2][2], P[2][3], st2);
    // final norm
    k_norm<<<(NN * FF / 4 + 255) / 256, 256>>>(st2, P[2][4], P[2][5], P[2][6],
                                               (float*)d_out);
}

// round 5
// speedup vs baseline: 1.2946x; 1.0005x over previous
#include <cuda_runtime.h>
#include <math_constants.h>

#define NN 50000
#define EE 800000
#define ETOT (EE + NN)
#define HC 128
#define FF 64
#define FULLMASK 0xffffffffu
#define NB 49  // ceil(NN/1024)

// ---------------- device scratch (static, no allocs) ----------------
__device__ int g_deg[NN];      // edge-only degree (self-loop added as +1 on read)
__device__ int g_cur[NN];
__device__ int g_off[NN + 1];
__device__ int g_bsum[64];
__device__ int g_srcs[ETOT];
__device__ float g_xl[(size_t)NN * HC];
__device__ float g_xr[(size_t)NN * HC];
__device__ float g_y[(size_t)NN * FF];
__device__ float g_stats[3][2 * FF];

// ---------------- CSR build ----------------
__global__ void k_hist(const int* __restrict__ ei) {
    int e = 4 * (blockIdx.x * blockDim.x + threadIdx.x);
    if (e < EE) {
        int4 d4 = *(const int4*)&ei[EE + e];
        atomicAdd(&g_deg[d4.x], 1);
        atomicAdd(&g_deg[d4.y], 1);
        atomicAdd(&g_deg[d4.z], 1);
        atomicAdd(&g_deg[d4.w], 1);
    }
}

// level 1: per-1024-block local inclusive scan of (deg+1) -> g_off[i+1], total -> g_bsum
__global__ void k_scan1() {
    __shared__ int wsum[32];
    int tid = threadIdx.x;
    int lane = tid & 31, wid = tid >> 5;
    int gi = blockIdx.x * 1024 + tid;
    int v = (gi < NN) ? (g_deg[gi] + 1) : 0;
    int s = v;
#pragma unroll
    for (int d = 1; d < 32; d <<= 1) {
        int t = __shfl_up_sync(FULLMASK, s, d);
        if (lane >= d) s += t;
    }
    if (lane == 31) wsum[wid] = s;
    __syncthreads();
    if (wid == 0) {
        int w = wsum[lane];
#pragma unroll
        for (int d = 1; d < 32; d <<= 1) {
            int t = __shfl_up_sync(FULLMASK, w, d);
            if (lane >= d) w += t;
        }
        wsum[lane] = w;
    }
    __syncthreads();
    int incl = s + (wid ? wsum[wid - 1] : 0);
    if (gi < NN) g_off[gi + 1] = incl;  // local inclusive, fixed up in scan3
    if (tid == 1023) g_bsum[blockIdx.x] = incl;
}

// level 2+3 merged: every block scans the 49 block sums itself, then fixes offsets
__global__ void k_scan3() {
    __shared__ int sh[64];
    int tid = threadIdx.x;
    if (tid < 64) sh[tid] = (tid < NB) ? g_bsum[tid] : 0;
    __syncthreads();
    if (tid < 32) {
        unsigned m = 0xffffffffu;
        int a = sh[tid], b = sh[tid + 32];
        int sa = a;
#pragma unroll
        for (int d = 1; d < 32; d <<= 1) {
            int t = __shfl_up_sync(m, sa, d);
            if ((tid & 31) >= d) sa += t;
        }
        int ta = __shfl_sync(m, sa, 31);
        int sb = b;
#pragma unroll
        for (int d = 1; d < 32; d <<= 1) {
            int t = __shfl_up_sync(m, sb, d);
            if ((tid & 31) >= d) sb += t;
        }
        sh[tid] = sa;
        sh[tid + 32] = sb + ta;
    }
    __syncthreads();
    int i = blockIdx.x * blockDim.x + tid;
    if (i < NN) {
        int blk = i >> 10;
        int pre = blk ? sh[blk - 1] : 0;
        int off = g_off[i + 1] + pre;
        g_off[i + 1] = off;
        g_cur[i] = off - g_deg[i] - 1;
    }
    if (i == 0) g_off[0] = 0;
}

// vectorized scatter: 4 edges per thread + self-loop tail
__global__ void k_scatter(const int* __restrict__ ei) {
    int t = blockIdx.x * blockDim.x + threadIdx.x;
    if (t < EE / 4) {
        int4 s4 = ((const int4*)ei)[t];
        int4 d4 = ((const int4*)(ei + EE))[t];
        g_srcs[atomicAdd(&g_cur[d4.x], 1)] = s4.x;
        g_srcs[atomicAdd(&g_cur[d4.y], 1)] = s4.y;
        g_srcs[atomicAdd(&g_cur[d4.z], 1)] = s4.z;
        g_srcs[atomicAdd(&g_cur[d4.w], 1)] = s4.w;
    } else {
        int v = t - EE / 4;
        if (v < NN) g_srcs[atomicAdd(&g_cur[v], 1)] = v;
    }
}

// ---------------- GEMM layer 1 (K=3, reads raw x) ----------------
__global__ void k_gemmA(const float* __restrict__ X,
                        const float* __restrict__ Wl,
                        const float* __restrict__ Wr) {
    __shared__ float sW[3][HC];
    __shared__ float sX[64][3];
    const float* W = (blockIdx.y == 0) ? Wl : Wr;
    float* out = (blockIdx.y == 0) ? g_xl : g_xr;
    int tid = threadIdx.x;
    int row0 = blockIdx.x * 64;

    for (int idx = tid; idx < 3 * HC; idx += 256)
        sW[idx / HC][idx % HC] = W[idx];
    for (int idx = tid; idx < 64 * 3; idx += 256) {
        int r = idx / 3, k = idx % 3;
        sX[r][k] = (row0 + r < NN) ? X[(size_t)(row0 + r) * 3 + k] : 0.f;
    }
    __syncthreads();

    int tx = tid & 31, ty = tid >> 5;
    float4 acc[8];
#pragma unroll
    for (int i = 0; i < 8; i++) acc[i] = make_float4(0.f, 0.f, 0.f, 0.f);
#pragma unroll
    for (int k = 0; k < 3; k++) {
        float4 b = *(const float4*)&sW[k][tx * 4];
#pragma unroll
        for (int i = 0; i < 8; i++) {
            float a = sX[ty * 8 + i][k];
            acc[i].x += a * b.x;
            acc[i].y += a * b.y;
            acc[i].z += a * b.z;
            acc[i].w += a * b.w;
        }
    }
#pragma unroll
    for (int i = 0; i < 8; i++) {
        int r = row0 + ty * 8 + i;
        if (r < NN) *(float4*)&out[(size_t)r * HC + tx * 4] = acc[i];
    }
}

// ---------------- GEMM layers 2,3 (K=64), fused GraphNorm+ReLU on X ----------------
#define SXIDX(k, r) (((k) << 6) + ((((((r) >> 1) ^ ((k) & 31))) << 1) | ((r) & 1)))

__global__ __launch_bounds__(256) void k_gemmB(
    const float* __restrict__ Wl, const float* __restrict__ Wr,
    const float* __restrict__ st, const float* __restrict__ gw,
    const float* __restrict__ gb, const float* __restrict__ gm) {
    __shared__ float sW[64 * HC];
    __shared__ float sX[64 * 64];
    __shared__ float sA[64], sB[64];
    int tid = threadIdx.x;
    const float* W = (blockIdx.y == 0) ? Wl : Wr;
    float* out = (blockIdx.y == 0) ? g_xl : g_xr;
    int row0 = blockIdx.x * 64;

    if (tid < 64) {
        const float invN = 1.f / (float)NN;
        float mu = st[tid] * invN;
        float ey2 = st[FF + tid] * invN;
        float gmc = gm[tid];
        float var = ey2 - 2.f * gmc * mu * mu + gmc * gmc * mu * mu;
        float al = gw[tid] * rsqrtf(var + 1e-5f);
        sA[tid] = al;
        sB[tid] = gb[tid] - al * gmc * mu;
    }
    for (int idx = tid; idx < 64 * HC; idx += 256) sW[idx] = W[idx];
    __syncthreads();
    for (int idx = tid; idx < 64 * 64; idx += 256) {
        int r = idx >> 6, k = idx & 63;
        float v = 0.f;
        if (row0 + r < NN) {
            float y = g_y[(size_t)(row0 + r) * FF + k];
            v = fmaxf(sA[k] * y + sB[k], 0.f);
        }
        sX[SXIDX(k, r)] = v;
    }
    __syncthreads();

    int tx = tid & 31, ty = tid >> 5;
    unsigned long long acc[4][4];
#pragma unroll
    for (int i = 0; i < 4; i++)
#pragma unroll
        for (int c = 0; c < 4; c++) acc[i][c] = 0ull;

#pragma unroll 4
    for (int k = 0; k < 64; k++) {
        float4 b4 = *(const float4*)&sW[k * HC + tx * 4];
        unsigned long long bs0, bs1, bs2, bs3;
        asm("mov.b64 %0, {%1,%1};" : "=l"(bs0) : "f"(b4.x));
        asm("mov.b64 %0, {%1,%1};" : "=l"(bs1) : "f"(b4.y));
        asm("mov.b64 %0, {%1,%1};" : "=l"(bs2) : "f"(b4.z));
        asm("mov.b64 %0, {%1,%1};" : "=l"(bs3) : "f"(b4.w));
#pragma unroll
        for (int i = 0; i < 4; i++) {
            unsigned long long a =
                *(const unsigned long long*)&sX[SXIDX(k, ty * 8 + 2 * i)];
            asm("fma.rn.f32x2 %0, %1, %2, %0;" : "+l"(acc[i][0]) : "l"(a), "l"(bs0));
            asm("fma.rn.f32x2 %0, %1, %2, %0;" : "+l"(acc[i][1]) : "l"(a), "l"(bs1));
            asm("fma.rn.f32x2 %0, %1, %2, %0;" : "+l"(acc[i][2]) : "l"(a), "l"(bs2));
            asm("fma.rn.f32x2 %0, %1, %2, %0;" : "+l"(acc[i][3]) : "l"(a), "l"(bs3));
        }
    }

#pragma unroll
    for (int i = 0; i < 4; i++) {
        int r = row0 + ty * 8 + 2 * i;
#pragma unroll
        for (int c = 0; c < 4; c++) {
            float lo, hi;
            asm("mov.b64 {%0,%1}, %2;" : "=f"(lo), "=f"(hi) : "l"(acc[i][c]));
            if (r < NN)     out[(size_t)r * HC + tx * 4 + c] = lo;
            if (r + 1 < NN) out[(size_t)(r + 1) * HC + tx * 4 + c] = hi;
        }
    }
}

// ---------------- edge kernel: warp per node, 2 edges/iter, 4-pair unroll, fused stats ----------------
__device__ __forceinline__ float ex2(float x) {
    float r;
    asm("ex2.approx.f32 %0, %1;" : "=f"(r) : "f"(x));
    return r;
}

__global__ __launch_bounds__(512) void k_edge(const float* __restrict__ att,
                                              const float* __restrict__ bias,
                                              float* __restrict__ st) {
    __shared__ float sS[2 * FF];
    int tid = threadIdx.x;
    if (tid < 2 * FF) sS[tid] = 0.f;
    __syncthreads();

    int warp = tid >> 5;
    int lane = tid & 31;
    int v = blockIdx.x * 16 + warp;  // grid sized so v < NN always
    int half = lane >> 4;
    int l16 = lane & 15;
    int ch0 = l16 * 8;

    const float LOG2E = 1.4426950408889634f;
    float4 attA = *(const float4*)&att[ch0];
    float4 attB = *(const float4*)&att[ch0 + 4];
    attA.x *= LOG2E; attA.y *= LOG2E; attA.z *= LOG2E; attA.w *= LOG2E;
    attB.x *= LOG2E; attB.y *= LOG2E; attB.z *= LOG2E; attB.w *= LOG2E;
    float4 xrA = *(const float4*)&g_xr[(size_t)v * HC + ch0];
    float4 xrB = *(const float4*)&g_xr[(size_t)v * HC + ch0 + 4];

    float z = 0.f;
    float4 accA = make_float4(0.f, 0.f, 0.f, 0.f);
    float4 accB = make_float4(0.f, 0.f, 0.f, 0.f);

#define PAIR(T)                                                                \
    {                                                                          \
        int eidx = 2 * (T) + half;                                             \
        bool valid = eidx < cnt;                                               \
        int s = __shfl_sync(FULLMASK, sb, eidx);                               \
        const float* xp = &g_xl[(size_t)s * HC + ch0];                         \
        float4 xa = *(const float4*)xp;                                        \
        float4 xb = *(const float4*)(xp + 4);                                  \
        float e, pa = 0.f, pb = 0.f;                                           \
        e = xa.x + xrA.x; e = fmaxf(e, 0.2f * e); pa = fmaf(e, attA.x, pa);    \
        e = xa.y + xrA.y; e = fmaxf(e, 0.2f * e); pa = fmaf(e, attA.y, pa);    \
        e = xa.z + xrA.z; e = fmaxf(e, 0.2f * e); pa = fmaf(e, attA.z, pa);    \
        e = xa.w + xrA.w; e = fmaxf(e, 0.2f * e); pa = fmaf(e, attA.w, pa);    \
        e = xb.x + xrB.x; e = fmaxf(e, 0.2f * e); pb = fmaf(e, attB.x, pb);    \
        e = xb.y + xrB.y; e = fmaxf(e, 0.2f * e); pb = fmaf(e, attB.y, pb);    \
        e = xb.z + xrB.z; e = fmaxf(e, 0.2f * e); pb = fmaf(e, attB.z, pb);    \
        e = xb.w + xrB.w; e = fmaxf(e, 0.2f * e); pb = fmaf(e, attB.w, pb);    \
        float p = pa + pb;                                                     \
        p += __shfl_xor_sync(FULLMASK, p, 4);                                  \
        p += __shfl_xor_sync(FULLMASK, p, 2);                                  \
        p += __shfl_xor_sync(FULLMASK, p, 1);                                  \
        float w = valid ? ex2(fminf(p, 126.f)) : 0.f;                          \
        z += w;                                                                \
        accA.x += w * xa.x; accA.y += w * xa.y;                                \
        accA.z += w * xa.z; accA.w += w * xa.w;                                \
        accB.x += w * xb.x; accB.y += w * xb.y;                                \
        accB.z += w * xb.z; accB.w += w * xb.w;                                \
    }

    int beg = g_off[v], end = g_off[v + 1];
    for (int base = beg; base < end; base += 32) {
        int idx = base + lane;
        int sb = (idx < end) ? g_srcs[idx] : 0;
        int cnt = min(32, end - base);
        int pairs = (cnt + 1) >> 1;
        int t = 0;
        for (; t + 4 <= pairs; t += 4) { PAIR(t) PAIR(t + 1) PAIR(t + 2) PAIR(t + 3) }
        for (; t < pairs; t++) PAIR(t)
    }
#undef PAIR

    z += __shfl_xor_sync(FULLMASK, z, 16);
    accA.x += __shfl_xor_sync(FULLMASK, accA.x, 16);
    accA.y += __shfl_xor_sync(FULLMASK, accA.y, 16);
    accA.z += __shfl_xor_sync(FULLMASK, accA.z, 16);
    accA.w += __shfl_xor_sync(FULLMASK, accA.w, 16);
    accB.x += __shfl_xor_sync(FULLMASK, accB.x, 16);
    accB.y += __shfl_xor_sync(FULLMASK, accB.y, 16);
    accB.z += __shfl_xor_sync(FULLMASK, accB.z, 16);
    accB.w += __shfl_xor_sync(FULLMASK, accB.w, 16);
    float inv = 1.f / z;
    float rA0 = accA.x * inv, rA1 = accA.y * inv, rA2 = accA.z * inv, rA3 = accA.w * inv;
    float rB0 = accB.x * inv, rB1 = accB.y * inv, rB2 = accB.z * inv, rB3 = accB.w * inv;
    float o0 = 0.5f * (rA0 + __shfl_xor_sync(FULLMASK, rA0, 8));
    float o1 = 0.5f * (rA1 + __shfl_xor_sync(FULLMASK, rA1, 8));
    float o2 = 0.5f * (rA2 + __shfl_xor_sync(FULLMASK, rA2, 8));
    float o3 = 0.5f * (rA3 + __shfl_xor_sync(FULLMASK, rA3, 8));
    float o4 = 0.5f * (rB0 + __shfl_xor_sync(FULLMASK, rB0, 8));
    float o5 = 0.5f * (rB1 + __shfl_xor_sync(FULLMASK, rB1, 8));
    float o6 = 0.5f * (rB2 + __shfl_xor_sync(FULLMASK, rB2, 8));
    float o7 = 0.5f * (rB3 + __shfl_xor_sync(FULLMASK, rB3, 8));

    if (half == 0 && l16 < 8) {
        float4 bbA = *(const float4*)&bias[ch0];
        float4 bbB = *(const float4*)&bias[ch0 + 4];
        o0 += bbA.x; o1 += bbA.y; o2 += bbA.z; o3 += bbA.w;
        o4 += bbB.x; o5 += bbB.y; o6 += bbB.z; o7 += bbB.w;
        *(float4*)&g_y[(size_t)v * FF + ch0] = make_float4(o0, o1, o2, o3);
        *(float4*)&g_y[(size_t)v * FF + ch0 + 4] = make_float4(o4, o5, o6, o7);
        atomicAdd(&sS[ch0 + 0], o0); atomicAdd(&sS[FF + ch0 + 0], o0 * o0);
        atomicAdd(&sS[ch0 + 1], o1); atomicAdd(&sS[FF + ch0 + 1], o1 * o1);
        atomicAdd(&sS[ch0 + 2], o2); atomicAdd(&sS[FF + ch0 + 2], o2 * o2);
        atomicAdd(&sS[ch0 + 3], o3); atomicAdd(&sS[FF + ch0 + 3], o3 * o3);
        atomicAdd(&sS[ch0 + 4], o4); atomicAdd(&sS[FF + ch0 + 4], o4 * o4);
        atomicAdd(&sS[ch0 + 5], o5); atomicAdd(&sS[FF + ch0 + 5], o5 * o5);
        atomicAdd(&sS[ch0 + 6], o6); atomicAdd(&sS[FF + ch0 + 6], o6 * o6);
        atomicAdd(&sS[ch0 + 7], o7); atomicAdd(&sS[FF + ch0 + 7], o7 * o7);
    }
    __syncthreads();
    if (tid < 2 * FF) atomicAdd(&st[tid], sS[tid]);
}

// ---------------- final norm (layer 3) -> d_out, float4 ----------------
__global__ void k_norm(const float* __restrict__ st, const float* __restrict__ gw,
                       const float* __restrict__ gb, const float* __restrict__ gm,
                       float* __restrict__ out) {
    __shared__ float sA[64], sB[64];
    int tid = threadIdx.x;
    if (tid < 64) {
        const float invN = 1.f / (float)NN;
        float mu = st[tid] * invN;
        float ey2 = st[FF + tid] * invN;
        float gmc = gm[tid];
        float var = ey2 - 2.f * gmc * mu * mu + gmc * gmc * mu * mu;
        float al = gw[tid] * rsqrtf(var + 1e-5f);
        sA[tid] = al;
        sB[tid] = gb[tid] - al * gmc * mu;
    }
    __syncthreads();
    int idx = blockIdx.x * blockDim.x + tid;
    if (idx >= NN * FF / 4) return;
    int c = (idx * 4) & 63;
    float4 y = *(const float4*)&g_y[idx * 4];
    float4 o;
    o.x = fmaxf(sA[c + 0] * y.x + sB[c + 0], 0.f);
    o.y = fmaxf(sA[c + 1] * y.y + sB[c + 1], 0.f);
    o.z = fmaxf(sA[c + 2] * y.z + sB[c + 2], 0.f);
    o.w = fmaxf(sA[c + 3] * y.w + sB[c + 3], 0.f);
    *(float4*)&out[idx * 4] = o;
}

// ---------------- launch ----------------
extern "C" void kernel_launch(void* const* d_in, const int* in_sizes, int n_in,
                              void* d_out, int out_size) {
    const float* x = (const float*)d_in[0];
    const int* ei = (const int*)d_in[1];
    const float* P[3][7];
    for (int l = 0; l < 3; l++)
        for (int j = 0; j < 7; j++)
            P[l][j] = (const float*)d_in[2 + l * 7 + j];
    // j: 0 Wl, 1 Wr, 2 att, 3 b, 4 gw, 5 gb, 6 gm

    static float* s_stats_base = nullptr;
    static int* s_deg_base = nullptr;
    static cudaStream_t s2 = nullptr;
    static cudaEvent_t evFork = nullptr, evJoin = nullptr;
    if (!s_stats_base) {
        void* p = nullptr;
        cudaGetSymbolAddress(&p, g_stats);
        s_stats_base = (float*)p;
        cudaGetSymbolAddress(&p, g_deg);
        s_deg_base = (int*)p;
        cudaStreamCreateWithFlags(&s2, cudaStreamNonBlocking);
        cudaEventCreateWithFlags(&evFork, cudaEventDisableTiming);
        cudaEventCreateWithFlags(&evJoin, cudaEventDisableTiming);
    }
    float* st0 = s_stats_base;
    float* st1 = s_stats_base + 2 * FF;
    float* st2 = s_stats_base + 4 * FF;

    dim3 ggrid((NN + 63) / 64, 2);
    int eblocks = (NN + 15) / 16;  // 3125

    // fork: gemmA on s2 concurrent with CSR build on main stream
    cudaEventRecord(evFork, 0);
    cudaStreamWaitEvent(s2, evFork, 0);
    k_gemmA<<<ggrid, 256, 0, s2>>>(x, P[0][0], P[0][1]);
    cudaEventRecord(evJoin, s2);

    // CSR build on main stream
    cudaMemsetAsync(s_deg_base, 0, NN * sizeof(int), 0);
    cudaMemsetAsync(s_stats_base, 0, 3 * 2 * FF * sizeof(float), 0);
    k_hist<<<(EE / 4 + 255) / 256, 256>>>(ei);
    k_scan1<<<NB, 1024>>>();
    k_scan3<<<(NN + 255) / 256, 256>>>();
    k_scatter<<<(EE / 4 + NN + 255) / 256, 256>>>(ei);

    // join
    cudaStreamWaitEvent(0, evJoin, 0);

    // layer 1
    k_edge<<<eblocks, 512>>>(P[0][2], P[0][3], st0);
    // layer 2 (norm of layer1 fused into gemm)
    k_gemmB<<<ggrid, 256>>>(P[1][0], P[1][1], st0, P[0][4], P[0][5], P[0][6]);
    k_edge<<<eblocks, 512>>>(P[1][2], P[1][3], st1);
    // layer 3
    k_gemmB<<<ggrid, 256>>>(P[2][0], P[2][1], st1, P[1][4], P[1][5], P[1][6]);
    k_edge<<<eblocks, 512>>>(P[2][2], P[2][3], st2);
    // final norm
    k_norm<<<(NN * FF / 4 + 255) / 256, 256>>>(st2, P[2][4], P[2][5], P[2][6],
                                               (float*)d_out);
}